// round 7
// baseline (speedup 1.0000x reference)
#include <cuda_runtime.h>
#include <cuda_bf16.h>
#include <math.h>
#include <stdint.h>

#define T_STEPS 16
#define IN_DIM  12288
#define H1 256
#define H2 512
#define BATCH 128
#define M_ROWS (T_STEPS * BATCH)   // 2048
#define NBLK 128
#define PITCH 40
#define STAGES 3

// ---------------- scratch (no cudaMalloc allowed) ----------------
__device__ float g_pre1[M_ROWS * 4 * H1];
__device__ float g_y1  [M_ROWS * H1];
__device__ float g_pre2[M_ROWS * 4 * H2];
__device__ float g_h1[2][H1 * BATCH];
__device__ float g_h2[2][H2 * BATCH];
__device__ unsigned g_cnt1, g_gen1, g_cnt2, g_gen2;

// split-bf16 operands, 3 segments along K:
//   A-side: [hi | lo | hi]   W-side: [hi | hi | lo]
__device__ __nv_bfloat16 g_A1s[M_ROWS * 3 * IN_DIM];
__device__ __nv_bfloat16 g_W1s[4 * H1 * 3 * IN_DIM];
__device__ __nv_bfloat16 g_y1s[M_ROWS * 3 * H1];
__device__ __nv_bfloat16 g_W2s[4 * H2 * 3 * H1];

// ---------------- fp32 -> split bf16 (3 segments along K) ----------------
__global__ void split_bf16(const float* __restrict__ src, __nv_bfloat16* __restrict__ dst,
                           int K, int a_mode) {
    int r = blockIdx.y;
    int k = (blockIdx.x * blockDim.x + threadIdx.x) * 4;
    if (k >= K) return;
    float4 a = *(const float4*)(src + (size_t)r * K + k);
    __nv_bfloat16* d0 = dst + (size_t)r * 3 * K + k;
    __nv_bfloat16* d1 = d0 + K;
    __nv_bfloat16* d2 = d0 + 2 * K;
    float v[4] = {a.x, a.y, a.z, a.w};
    #pragma unroll
    for (int i = 0; i < 4; ++i) {
        __nv_bfloat16 hi = __float2bfloat16(v[i]);
        __nv_bfloat16 lo = __float2bfloat16(v[i] - __bfloat162float(hi));
        d0[i] = hi;
        if (a_mode) { d1[i] = lo; d2[i] = hi; }
        else        { d1[i] = hi; d2[i] = lo; }
    }
}

// ---------------- PTX helpers ----------------
__device__ __forceinline__ uint32_t smem_u32(const void* p) {
    uint32_t a;
    asm("{ .reg .u64 t; cvta.to.shared.u64 t, %1; cvt.u32.u64 %0, t; }" : "=r"(a) : "l"(p));
    return a;
}
__device__ __forceinline__ void ldsm_x4(uint32_t& r0, uint32_t& r1, uint32_t& r2, uint32_t& r3, uint32_t a) {
    asm volatile("ldmatrix.sync.aligned.m8n8.x4.shared.b16 {%0,%1,%2,%3}, [%4];"
                 : "=r"(r0), "=r"(r1), "=r"(r2), "=r"(r3) : "r"(a));
}
__device__ __forceinline__ void mma16816(float* c, const uint32_t* a, const uint32_t* b) {
    asm volatile(
        "mma.sync.aligned.m16n8k16.row.col.f32.bf16.bf16.f32 "
        "{%0,%1,%2,%3}, {%4,%5,%6,%7}, {%8,%9}, {%0,%1,%2,%3};"
        : "+f"(c[0]), "+f"(c[1]), "+f"(c[2]), "+f"(c[3])
        : "r"(a[0]), "r"(a[1]), "r"(a[2]), "r"(a[3]), "r"(b[0]), "r"(b[1]));
}
__device__ __forceinline__ void cp16(uint32_t saddr, const void* gaddr) {
    asm volatile("cp.async.cg.shared.global [%0], [%1], 16;" :: "r"(saddr), "l"(gaddr));
}

// ---------------- HMMA GEMM with cp.async 3-stage pipeline ----------------
// C[M,N] = A[M,K2] @ W[N,K2]^T + bias. 128x128 CTA tile, BK=32, 8 warps.
__global__ __launch_bounds__(256) void gemm_hmma(
    const __nv_bfloat16* __restrict__ A, const __nv_bfloat16* __restrict__ W,
    const float* __restrict__ bias, float* __restrict__ C, int N, int K2)
{
    extern __shared__ __nv_bfloat16 smb[];   // [STAGES][A:5120 | B:5120] elems
    const int TILE_E = 128 * PITCH;          // 5120 elems = 10240 B

    const int tid = threadIdx.x;
    const int lane = tid & 31;
    const int wid = tid >> 5;
    const int moff = (wid >> 1) * 32;
    const int noff = (wid & 1) * 64;
    const int m0 = blockIdx.y * 128;
    const int n0 = blockIdx.x * 128;
    const int NT = K2 >> 5;

    const int r0g = tid >> 2, c0g = (tid & 3) * 8;
    const int r1g = r0g + 64;

    float acc[2][8][4];
    #pragma unroll
    for (int mt = 0; mt < 2; ++mt)
        #pragma unroll
        for (int nt = 0; nt < 8; ++nt)
            #pragma unroll
            for (int i = 0; i < 4; ++i) acc[mt][nt][i] = 0.f;

    const __nv_bfloat16* Ab = A + (size_t)m0 * K2;
    const __nv_bfloat16* Wb = W + (size_t)n0 * K2;

    const uint32_t sA0 = smem_u32(&smb[r0g * PITCH + c0g]);
    const uint32_t sA1 = smem_u32(&smb[r1g * PITCH + c0g]);

    // issue cp.async group for k-tile kt into stage kt%STAGES
    #define ISSUE(kt) do {                                                    \
        int _s = (kt) % STAGES;                                               \
        uint32_t _b = (uint32_t)_s * 2u * TILE_E * 2u;                        \
        int _k0 = (kt) << 5;                                                  \
        cp16(sA0 + _b,              Ab + (size_t)r0g * K2 + _k0 + c0g);       \
        cp16(sA1 + _b,              Ab + (size_t)r1g * K2 + _k0 + c0g);       \
        cp16(sA0 + _b + TILE_E*2u,  Wb + (size_t)r0g * K2 + _k0 + c0g);       \
        cp16(sA1 + _b + TILE_E*2u,  Wb + (size_t)r1g * K2 + _k0 + c0g);       \
        asm volatile("cp.async.commit_group;" ::: "memory");                  \
    } while (0)

    ISSUE(0);
    ISSUE(1);

    const int lrow = lane & 15;
    const int lhalf = (lane >> 4) * 8;
    const uint32_t smbase = smem_u32(smb);

    for (int kt = 0; kt < NT; ++kt) {
        asm volatile("cp.async.wait_group 1;" ::: "memory");
        __syncthreads();

        const int cur = kt % STAGES;
        const uint32_t sA = smbase + (uint32_t)cur * 2u * TILE_E * 2u;
        const uint32_t sB = sA + TILE_E * 2u;

        #pragma unroll
        for (int ks = 0; ks < 32; ks += 16) {
            uint32_t af[2][4];
            #pragma unroll
            for (int mt = 0; mt < 2; ++mt) {
                uint32_t addr = sA + (uint32_t)((moff + mt * 16 + lrow) * PITCH + ks + lhalf) * 2u;
                ldsm_x4(af[mt][0], af[mt][1], af[mt][2], af[mt][3], addr);
            }
            uint32_t bf[8][2];
            #pragma unroll
            for (int nt2 = 0; nt2 < 4; ++nt2) {
                uint32_t t0, t1, t2, t3;
                uint32_t addr = sB + (uint32_t)((noff + nt2 * 16 + lrow) * PITCH + ks + lhalf) * 2u;
                ldsm_x4(t0, t1, t2, t3, addr);
                bf[nt2 * 2 + 0][0] = t0; bf[nt2 * 2 + 0][1] = t2;
                bf[nt2 * 2 + 1][0] = t1; bf[nt2 * 2 + 1][1] = t3;
            }
            #pragma unroll
            for (int mt = 0; mt < 2; ++mt)
                #pragma unroll
                for (int nt = 0; nt < 8; ++nt)
                    mma16816(acc[mt][nt], af[mt], bf[nt]);
        }

        if (kt + 2 < NT) {
            ISSUE(kt + 2);
        } else {
            asm volatile("cp.async.commit_group;" ::: "memory");
        }
    }
    #undef ISSUE

    // epilogue: add bias, write C
    const int g = lane >> 2;
    const int tig = lane & 3;
    #pragma unroll
    for (int mt = 0; mt < 2; ++mt) {
        #pragma unroll
        for (int nt = 0; nt < 8; ++nt) {
            int n = n0 + noff + nt * 8 + tig * 2;
            float b0v = bias[n], b1v = bias[n + 1];
            int mA = m0 + moff + mt * 16 + g;
            float2 v0 = { acc[mt][nt][0] + b0v, acc[mt][nt][1] + b1v };
            float2 v1 = { acc[mt][nt][2] + b0v, acc[mt][nt][3] + b1v };
            *(float2*)(C + (size_t)mA * N + n) = v0;
            *(float2*)(C + (size_t)(mA + 8) * N + n) = v1;
        }
    }
}

// ---------------- grid barrier (volatile spin) ----------------
__device__ __forceinline__ void grid_sync(unsigned* cnt, unsigned* gen, unsigned& local) {
    __syncthreads();
    if (threadIdx.x == 0) {
        __threadfence();
        if (atomicAdd(cnt, 1u) == NBLK - 1u) {
            atomicExch(cnt, 0u);
            __threadfence();
            atomicAdd(gen, 1u);
        } else {
            while (*(volatile unsigned*)gen == local) { }
        }
        __threadfence();
    }
    __syncthreads();
    local++;
}

__device__ __forceinline__ float sigf(float x) { return 1.f / (1.f + expf(-x)); }

// ---------------- persistent LSTM layer 1 (H=256), direct-gmem h ----------------
__global__ __launch_bounds__(256) void lstm_layer1(
    const float* __restrict__ pre, const float* __restrict__ Whh, float* __restrict__ y1)
{
    __shared__ float Wst[H1 * 8];    // 8 KB
    __shared__ unsigned s_gen;

    const int tid = threadIdx.x;
    const int bid = blockIdx.x;
    const int b   = tid & 127;
    const int jj  = tid >> 7;
    const int j   = bid * 2 + jj;

    #pragma unroll
    for (int r = 0; r < 8; ++r) {
        int jj2 = r >> 2, g = r & 3;
        const float* wrow = Whh + ((size_t)(g * H1 + bid * 2 + jj2)) * H1;
        for (int k = tid; k < H1; k += 256) Wst[k * 8 + jj2 * 4 + g] = wrow[k];
    }
    if (tid == 0) s_gen = atomicAdd(&g_gen1, 0u);
    __syncthreads();
    unsigned local = s_gen;

    float c0 = 0.f;

    for (int t = 0; t < T_STEPS; ++t) {
        float a0 = 0.f, a1 = 0.f, a2 = 0.f, a3 = 0.f;
        if (t > 0) {
            const float* hp = g_h1[(t - 1) & 1];
            #pragma unroll 8
            for (int k = 0; k < H1; ++k) {
                float hv = __ldg(hp + k * BATCH + b);
                float4 w = *(const float4*)&Wst[k * 8 + jj * 4];
                a0 += w.x * hv; a1 += w.y * hv; a2 += w.z * hv; a3 += w.w * hv;
            }
        }
        const float* p = pre + ((size_t)t * BATCH + b) * (4 * H1);
        float ig = a0 + __ldg(p + j);
        float fg = a1 + __ldg(p + H1 + j);
        float gg = a2 + __ldg(p + 2 * H1 + j);
        float og = a3 + __ldg(p + 3 * H1 + j);
        c0 = sigf(fg) * c0 + sigf(ig) * tanhf(gg);
        float h2 = sigf(og) * tanhf(c0);
        y1[((size_t)t * BATCH + b) * H1 + j] = h2;
        if (t < T_STEPS - 1) {
            g_h1[t & 1][j * BATCH + b] = h2;
            grid_sync(&g_cnt1, &g_gen1, local);
        }
    }
}

// ---------------- persistent LSTM layer 2 (H=512), direct-gmem h ----------------
__global__ __launch_bounds__(256) void lstm_layer2(
    const float* __restrict__ pre, const float* __restrict__ Whh, float* __restrict__ out)
{
    __shared__ float Wst[H2 * 16];   // 32 KB
    __shared__ unsigned s_gen;

    const int tid = threadIdx.x;
    const int bid = blockIdx.x;
    const int b   = tid & 127;
    const int jp  = tid >> 7;

    #pragma unroll
    for (int r = 0; r < 16; ++r) {
        int jj = r >> 2, g = r & 3;
        const float* wrow = Whh + ((size_t)(g * H2 + bid * 4 + jj)) * H2;
        for (int k = tid; k < H2; k += 256) Wst[k * 16 + jj * 4 + g] = wrow[k];
    }
    if (tid == 0) s_gen = atomicAdd(&g_gen2, 0u);
    __syncthreads();
    unsigned local = s_gen;

    float c0 = 0.f, c1 = 0.f;

    for (int t = 0; t < T_STEPS; ++t) {
        float acc[8];
        #pragma unroll
        for (int i = 0; i < 8; ++i) acc[i] = 0.f;

        if (t > 0) {
            const float* hp = g_h2[(t - 1) & 1];
            #pragma unroll 4
            for (int k = 0; k < H2; ++k) {
                float hv = __ldg(hp + k * BATCH + b);
                const float* wp = &Wst[k * 16 + jp * 8];
                float4 wa = *(const float4*)(wp);
                float4 wb = *(const float4*)(wp + 4);
                acc[0] += wa.x * hv; acc[1] += wa.y * hv;
                acc[2] += wa.z * hv; acc[3] += wa.w * hv;
                acc[4] += wb.x * hv; acc[5] += wb.y * hv;
                acc[6] += wb.z * hv; acc[7] += wb.w * hv;
            }
        }

        const float* p = pre + ((size_t)t * BATCH + b) * (4 * H2);
        #pragma unroll
        for (int u = 0; u < 2; ++u) {
            int j = bid * 4 + jp * 2 + u;
            float ig = acc[u * 4 + 0] + __ldg(p + j);
            float fg = acc[u * 4 + 1] + __ldg(p + H2 + j);
            float gg = acc[u * 4 + 2] + __ldg(p + 2 * H2 + j);
            float og = acc[u * 4 + 3] + __ldg(p + 3 * H2 + j);
            float c = (u == 0) ? c0 : c1;
            c = sigf(fg) * c + sigf(ig) * tanhf(gg);
            if (u == 0) c0 = c; else c1 = c;
            float h2 = sigf(og) * tanhf(c);
            out[((size_t)t * BATCH + b) * H2 + j] = h2;
            if (t < T_STEPS - 1) g_h2[t & 1][j * BATCH + b] = h2;
        }
        if (t < T_STEPS - 1) grid_sync(&g_cnt2, &g_gen2, local);
    }
}

// ---------------- launch ----------------
extern "C" void kernel_launch(void* const* d_in, const int* in_sizes, int n_in,
                              void* d_out, int out_size)
{
    const float* inp  = (const float*)d_in[0];
    const float* Wih1 = (const float*)d_in[1];
    const float* Whh1 = (const float*)d_in[2];
    const float* b1   = (const float*)d_in[3];
    const float* Wih2 = (const float*)d_in[4];
    const float* Whh2 = (const float*)d_in[5];
    const float* b2   = (const float*)d_in[6];
    float* out = (float*)d_out;

    float *pre1, *y1, *pre2;
    __nv_bfloat16 *A1s, *W1s, *y1s, *W2s;
    cudaGetSymbolAddress((void**)&pre1, g_pre1);
    cudaGetSymbolAddress((void**)&y1,   g_y1);
    cudaGetSymbolAddress((void**)&pre2, g_pre2);
    cudaGetSymbolAddress((void**)&A1s,  g_A1s);
    cudaGetSymbolAddress((void**)&W1s,  g_W1s);
    cudaGetSymbolAddress((void**)&y1s,  g_y1s);
    cudaGetSymbolAddress((void**)&W2s,  g_W2s);

    const int gemm_smem = STAGES * 2 * 128 * PITCH * 2;   // 61440 B
    cudaFuncSetAttribute(gemm_hmma, cudaFuncAttributeMaxDynamicSharedMemorySize, gemm_smem);

    // ---- layer 1 ----
    split_bf16<<<dim3(IN_DIM / 1024, M_ROWS), 256>>>(inp, A1s, IN_DIM, 1);
    split_bf16<<<dim3(IN_DIM / 1024, 4 * H1), 256>>>(Wih1, W1s, IN_DIM, 0);
    gemm_hmma<<<dim3(4 * H1 / 128, M_ROWS / 128), 256, gemm_smem>>>(
        A1s, W1s, b1, pre1, 4 * H1, 3 * IN_DIM);

    lstm_layer1<<<NBLK, 256>>>(pre1, Whh1, y1);

    // ---- layer 2 ----
    split_bf16<<<dim3(1, M_ROWS), 256>>>(y1, y1s, H1, 1);
    split_bf16<<<dim3(1, 4 * H2), 256>>>(Wih2, W2s, H1, 0);
    gemm_hmma<<<dim3(4 * H2 / 128, M_ROWS / 128), 256, gemm_smem>>>(
        y1s, W2s, b2, pre2, 4 * H2, 3 * H1);

    lstm_layer2<<<NBLK, 256>>>(pre2, Whh2, out);
}

// round 11
// speedup vs baseline: 1.6428x; 1.6428x over previous
#include <cuda_runtime.h>
#include <cuda_bf16.h>
#include <math.h>
#include <stdint.h>

#define T_STEPS 16
#define IN_DIM  12288
#define H1 256
#define H2 512
#define BATCH 128
#define M_ROWS (T_STEPS * BATCH)   // 2048
#define NBLK 128
#define PITCH 40

// ---------------- scratch (no cudaMalloc allowed) ----------------
__device__ float g_pre1[M_ROWS * 4 * H1];
__device__ float g_y1  [M_ROWS * H1];
__device__ float g_pre2[M_ROWS * 4 * H2];
__device__ float g_h1[2][H1 * BATCH];
__device__ float g_h2[2][H2 * BATCH];
__device__ unsigned g_cnt1, g_gen1, g_cnt2, g_gen2;

// split-bf16 operands, 3 segments along K:
//   A-side: [hi | lo | hi]   W-side: [hi | hi | lo]
__device__ __nv_bfloat16 g_A1s[M_ROWS * 3 * IN_DIM];
__device__ __nv_bfloat16 g_W1s[4 * H1 * 3 * IN_DIM];
__device__ __nv_bfloat16 g_y1s[M_ROWS * 3 * H1];
__device__ __nv_bfloat16 g_W2s[4 * H2 * 3 * H1];

// ---------------- fp32 -> split bf16 (3 segments along K) ----------------
__global__ void split_bf16(const float* __restrict__ src, __nv_bfloat16* __restrict__ dst,
                           int K, int a_mode) {
    int r = blockIdx.y;
    int k = (blockIdx.x * blockDim.x + threadIdx.x) * 4;
    if (k >= K) return;
    float4 a = *(const float4*)(src + (size_t)r * K + k);
    __nv_bfloat16* d0 = dst + (size_t)r * 3 * K + k;
    __nv_bfloat16* d1 = d0 + K;
    __nv_bfloat16* d2 = d0 + 2 * K;
    float v[4] = {a.x, a.y, a.z, a.w};
    #pragma unroll
    for (int i = 0; i < 4; ++i) {
        __nv_bfloat16 hi = __float2bfloat16(v[i]);
        __nv_bfloat16 lo = __float2bfloat16(v[i] - __bfloat162float(hi));
        d0[i] = hi;
        if (a_mode) { d1[i] = lo; d2[i] = hi; }
        else        { d1[i] = hi; d2[i] = lo; }
    }
}

// ---------------- PTX helpers ----------------
__device__ __forceinline__ uint32_t smem_u32(const void* p) {
    uint32_t a;
    asm("{ .reg .u64 t; cvta.to.shared.u64 t, %1; cvt.u32.u64 %0, t; }" : "=r"(a) : "l"(p));
    return a;
}
__device__ __forceinline__ void ldsm_x4(uint32_t& r0, uint32_t& r1, uint32_t& r2, uint32_t& r3, uint32_t a) {
    asm volatile("ldmatrix.sync.aligned.m8n8.x4.shared.b16 {%0,%1,%2,%3}, [%4];"
                 : "=r"(r0), "=r"(r1), "=r"(r2), "=r"(r3) : "r"(a));
}
__device__ __forceinline__ void mma16816(float* c, const uint32_t* a, const uint32_t* b) {
    asm volatile(
        "mma.sync.aligned.m16n8k16.row.col.f32.bf16.bf16.f32 "
        "{%0,%1,%2,%3}, {%4,%5,%6,%7}, {%8,%9}, {%0,%1,%2,%3};"
        : "+f"(c[0]), "+f"(c[1]), "+f"(c[2]), "+f"(c[3])
        : "r"(a[0]), "r"(a[1]), "r"(a[2]), "r"(a[3]), "r"(b[0]), "r"(b[1]));
}

// ---------------- HMMA GEMM: C[M,N] = A[M,K2] @ W[N,K2]^T + bias ----------------
// 128x64 CTA tile (2+ CTAs/SM for latency overlap), BK=32, 8 warps (4M x 2N),
// warp tile 32x32. Register-prefetch double buffer (round-5 proven structure).
__global__ __launch_bounds__(256) void gemm_hmma(
    const __nv_bfloat16* __restrict__ A, const __nv_bfloat16* __restrict__ W,
    const float* __restrict__ bias, float* __restrict__ C, int N, int K2)
{
    __shared__ __nv_bfloat16 As[2][128 * PITCH];   // 20480 B
    __shared__ __nv_bfloat16 Bs[2][64 * PITCH];    // 10240 B

    const int tid = threadIdx.x;
    const int lane = tid & 31;
    const int wid = tid >> 5;
    const int moff = (wid >> 1) * 32;
    const int noff = (wid & 1) * 32;
    const int m0 = blockIdx.y * 128;
    const int n0 = blockIdx.x * 64;
    const int NT = K2 >> 5;

    const int r0g = tid >> 2, c0g = (tid & 3) * 8;   // A rows 0..63 / B rows 0..63
    const int r1g = r0g + 64;                        // A rows 64..127

    float acc[2][4][4];
    #pragma unroll
    for (int mt = 0; mt < 2; ++mt)
        #pragma unroll
        for (int nt = 0; nt < 4; ++nt)
            #pragma unroll
            for (int i = 0; i < 4; ++i) acc[mt][nt][i] = 0.f;

    uint4 ra0, ra1, rb0;
    const __nv_bfloat16* Ab = A + (size_t)m0 * K2;
    const __nv_bfloat16* Wb = W + (size_t)n0 * K2;

    // prologue: tile 0 -> regs -> smem[0]
    ra0 = *(const uint4*)(Ab + (size_t)r0g * K2 + c0g);
    ra1 = *(const uint4*)(Ab + (size_t)r1g * K2 + c0g);
    rb0 = *(const uint4*)(Wb + (size_t)r0g * K2 + c0g);
    *(uint4*)&As[0][r0g * PITCH + c0g] = ra0;
    *(uint4*)&As[0][r1g * PITCH + c0g] = ra1;
    *(uint4*)&Bs[0][r0g * PITCH + c0g] = rb0;
    __syncthreads();

    const int lrow = lane & 15;
    const int lhalf = (lane >> 4) * 8;

    for (int kt = 0; kt < NT; ++kt) {
        const int cur = kt & 1;

        if (kt + 1 < NT) {
            const int k0 = (kt + 1) << 5;
            ra0 = *(const uint4*)(Ab + (size_t)r0g * K2 + k0 + c0g);
            ra1 = *(const uint4*)(Ab + (size_t)r1g * K2 + k0 + c0g);
            rb0 = *(const uint4*)(Wb + (size_t)r0g * K2 + k0 + c0g);
        }

        const uint32_t sA = smem_u32(&As[cur][0]);
        const uint32_t sB = smem_u32(&Bs[cur][0]);

        #pragma unroll
        for (int ks = 0; ks < 32; ks += 16) {
            uint32_t af[2][4];
            #pragma unroll
            for (int mt = 0; mt < 2; ++mt) {
                uint32_t addr = sA + (uint32_t)((moff + mt * 16 + lrow) * PITCH + ks + lhalf) * 2u;
                ldsm_x4(af[mt][0], af[mt][1], af[mt][2], af[mt][3], addr);
            }
            uint32_t bf[4][2];
            #pragma unroll
            for (int nt2 = 0; nt2 < 2; ++nt2) {
                uint32_t t0, t1, t2, t3;
                uint32_t addr = sB + (uint32_t)((noff + nt2 * 16 + lrow) * PITCH + ks + lhalf) * 2u;
                ldsm_x4(t0, t1, t2, t3, addr);   // NON-trans: W rows are n, k contiguous
                bf[nt2 * 2 + 0][0] = t0; bf[nt2 * 2 + 0][1] = t2;
                bf[nt2 * 2 + 1][0] = t1; bf[nt2 * 2 + 1][1] = t3;
            }
            #pragma unroll
            for (int mt = 0; mt < 2; ++mt)
                #pragma unroll
                for (int nt = 0; nt < 4; ++nt)
                    mma16816(acc[mt][nt], af[mt], bf[nt]);
        }

        if (kt + 1 < NT) {
            const int nxt = cur ^ 1;
            *(uint4*)&As[nxt][r0g * PITCH + c0g] = ra0;
            *(uint4*)&As[nxt][r1g * PITCH + c0g] = ra1;
            *(uint4*)&Bs[nxt][r0g * PITCH + c0g] = rb0;
        }
        __syncthreads();
    }

    // epilogue: add bias, write C
    const int g = lane >> 2;
    const int tig = lane & 3;
    #pragma unroll
    for (int mt = 0; mt < 2; ++mt) {
        #pragma unroll
        for (int nt = 0; nt < 4; ++nt) {
            int n = n0 + noff + nt * 8 + tig * 2;
            float b0v = bias[n], b1v = bias[n + 1];
            int mA = m0 + moff + mt * 16 + g;
            float2 v0 = { acc[mt][nt][0] + b0v, acc[mt][nt][1] + b1v };
            float2 v1 = { acc[mt][nt][2] + b0v, acc[mt][nt][3] + b1v };
            *(float2*)(C + (size_t)mA * N + n) = v0;
            *(float2*)(C + (size_t)(mA + 8) * N + n) = v1;
        }
    }
}

// ---------------- grid barrier ----------------
__device__ __forceinline__ void grid_sync(unsigned* cnt, unsigned* gen, unsigned& local) {
    __syncthreads();
    if (threadIdx.x == 0) {
        __threadfence();
        if (atomicAdd(cnt, 1u) == NBLK - 1u) {
            atomicExch(cnt, 0u);
            __threadfence();
            atomicAdd(gen, 1u);
        } else {
            while (atomicAdd(gen, 0u) == local) { }
        }
        __threadfence();
    }
    __syncthreads();
    local++;
}

__device__ __forceinline__ float sigf(float x) { return 1.f / (1.f + expf(-x)); }

// ---------------- persistent LSTM layer 1 (H=256) — round-5 proven ----------------
__global__ __launch_bounds__(256) void lstm_layer1(
    const float* __restrict__ pre, const float* __restrict__ Whh, float* __restrict__ y1)
{
    extern __shared__ float smemf[];
    float* Wst = smemf;
    float* hs  = smemf + H1 * 8;

    const int tid = threadIdx.x;
    const int bid = blockIdx.x;
    const int b   = tid & 127;
    const int jj  = tid >> 7;
    const int j   = bid * 2 + jj;

    #pragma unroll
    for (int r = 0; r < 8; ++r) {
        int jj2 = r >> 2, g = r & 3;
        const float* wrow = Whh + ((size_t)(g * H1 + bid * 2 + jj2)) * H1;
        for (int k = tid; k < H1; k += 256) Wst[k * 8 + jj2 * 4 + g] = wrow[k];
    }

    __shared__ unsigned s_gen;
    if (tid == 0) s_gen = atomicAdd(&g_gen1, 0u);
    __syncthreads();
    unsigned local = s_gen;

    float c0 = 0.f;

    for (int t = 0; t < T_STEPS; ++t) {
        float a0 = 0.f, a1 = 0.f, a2 = 0.f, a3 = 0.f;
        if (t > 0) {
            const float* hprev = g_h1[(t - 1) & 1];
            for (int k0 = 0; k0 < H1; k0 += 64) {
                const float4* src = (const float4*)(hprev + k0 * BATCH);
                float4* dst = (float4*)hs;
                #pragma unroll
                for (int i = tid; i < 64 * BATCH / 4; i += 256) dst[i] = src[i];
                __syncthreads();
                #pragma unroll 8
                for (int kk = 0; kk < 64; ++kk) {
                    float hv = hs[kk * BATCH + b];
                    float4 w = *(const float4*)(Wst + (size_t)(k0 + kk) * 8 + jj * 4);
                    a0 += w.x * hv; a1 += w.y * hv; a2 += w.z * hv; a3 += w.w * hv;
                }
                __syncthreads();
            }
        }
        const float* p = pre + ((size_t)t * BATCH + b) * (4 * H1);
        float ig = a0 + p[j];
        float fg = a1 + p[H1 + j];
        float gg = a2 + p[2 * H1 + j];
        float og = a3 + p[3 * H1 + j];
        c0 = sigf(fg) * c0 + sigf(ig) * tanhf(gg);
        float h2 = sigf(og) * tanhf(c0);
        y1[((size_t)t * BATCH + b) * H1 + j] = h2;
        if (t < T_STEPS - 1) {
            g_h1[t & 1][j * BATCH + b] = h2;
            grid_sync(&g_cnt1, &g_gen1, local);
        }
    }
}

// ---------------- persistent LSTM layer 2 (H=512) — round-5 proven ----------------
__global__ __launch_bounds__(256) void lstm_layer2(
    const float* __restrict__ pre, const float* __restrict__ Whh, float* __restrict__ out)
{
    extern __shared__ float smemf[];
    float* Wst = smemf;
    float* hs  = smemf + H2 * 16;

    const int tid = threadIdx.x;
    const int bid = blockIdx.x;
    const int b   = tid & 127;
    const int jp  = tid >> 7;

    #pragma unroll
    for (int r = 0; r < 16; ++r) {
        int jj = r >> 2, g = r & 3;
        const float* wrow = Whh + ((size_t)(g * H2 + bid * 4 + jj)) * H2;
        for (int k = tid; k < H2; k += 256) Wst[k * 16 + jj * 4 + g] = wrow[k];
    }

    __shared__ unsigned s_gen;
    if (tid == 0) s_gen = atomicAdd(&g_gen2, 0u);
    __syncthreads();
    unsigned local = s_gen;

    float c0 = 0.f, c1 = 0.f;

    for (int t = 0; t < T_STEPS; ++t) {
        float acc[8];
        #pragma unroll
        for (int i = 0; i < 8; ++i) acc[i] = 0.f;

        if (t > 0) {
            const float* hprev = g_h2[(t - 1) & 1];
            for (int k0 = 0; k0 < H2; k0 += 64) {
                const float4* src = (const float4*)(hprev + k0 * BATCH);
                float4* dst = (float4*)hs;
                #pragma unroll
                for (int i = tid; i < 64 * BATCH / 4; i += 256) dst[i] = src[i];
                __syncthreads();
                #pragma unroll 4
                for (int kk = 0; kk < 64; ++kk) {
                    float hv = hs[kk * BATCH + b];
                    const float* wp = Wst + (size_t)(k0 + kk) * 16 + jp * 8;
                    float4 wa = *(const float4*)(wp);
                    float4 wb = *(const float4*)(wp + 4);
                    acc[0] += wa.x * hv; acc[1] += wa.y * hv;
                    acc[2] += wa.z * hv; acc[3] += wa.w * hv;
                    acc[4] += wb.x * hv; acc[5] += wb.y * hv;
                    acc[6] += wb.z * hv; acc[7] += wb.w * hv;
                }
                __syncthreads();
            }
        }

        const float* p = pre + ((size_t)t * BATCH + b) * (4 * H2);
        #pragma unroll
        for (int u = 0; u < 2; ++u) {
            int j = bid * 4 + jp * 2 + u;
            float ig = acc[u * 4 + 0] + p[j];
            float fg = acc[u * 4 + 1] + p[H2 + j];
            float gg = acc[u * 4 + 2] + p[2 * H2 + j];
            float og = acc[u * 4 + 3] + p[3 * H2 + j];
            float c = (u == 0) ? c0 : c1;
            c = sigf(fg) * c + sigf(ig) * tanhf(gg);
            if (u == 0) c0 = c; else c1 = c;
            float h2 = sigf(og) * tanhf(c);
            out[((size_t)t * BATCH + b) * H2 + j] = h2;
            if (t < T_STEPS - 1) g_h2[t & 1][j * BATCH + b] = h2;
        }
        if (t < T_STEPS - 1) grid_sync(&g_cnt2, &g_gen2, local);
    }
}

// ---------------- launch ----------------
extern "C" void kernel_launch(void* const* d_in, const int* in_sizes, int n_in,
                              void* d_out, int out_size)
{
    const float* inp  = (const float*)d_in[0];
    const float* Wih1 = (const float*)d_in[1];
    const float* Whh1 = (const float*)d_in[2];
    const float* b1   = (const float*)d_in[3];
    const float* Wih2 = (const float*)d_in[4];
    const float* Whh2 = (const float*)d_in[5];
    const float* b2   = (const float*)d_in[6];
    float* out = (float*)d_out;

    float *pre1, *y1, *pre2;
    __nv_bfloat16 *A1s, *W1s, *y1s, *W2s;
    cudaGetSymbolAddress((void**)&pre1, g_pre1);
    cudaGetSymbolAddress((void**)&y1,   g_y1);
    cudaGetSymbolAddress((void**)&pre2, g_pre2);
    cudaGetSymbolAddress((void**)&A1s,  g_A1s);
    cudaGetSymbolAddress((void**)&W1s,  g_W1s);
    cudaGetSymbolAddress((void**)&y1s,  g_y1s);
    cudaGetSymbolAddress((void**)&W2s,  g_W2s);

    const int smem1 = (H1 * 8 + 64 * BATCH) * sizeof(float);
    const int smem2 = (H2 * 16 + 64 * BATCH) * sizeof(float);
    cudaFuncSetAttribute(lstm_layer2, cudaFuncAttributeMaxDynamicSharedMemorySize, smem2);

    // ---- layer 1 ----
    split_bf16<<<dim3(IN_DIM / 1024, M_ROWS), 256>>>(inp, A1s, IN_DIM, 1);
    split_bf16<<<dim3(IN_DIM / 1024, 4 * H1), 256>>>(Wih1, W1s, IN_DIM, 0);
    gemm_hmma<<<dim3(4 * H1 / 64, M_ROWS / 128), 256>>>(
        A1s, W1s, b1, pre1, 4 * H1, 3 * IN_DIM);

    lstm_layer1<<<NBLK, 256, smem1>>>(pre1, Whh1, y1);

    // ---- layer 2 ----
    split_bf16<<<dim3(1, M_ROWS), 256>>>(y1, y1s, H1, 1);
    split_bf16<<<dim3(1, 4 * H2), 256>>>(Wih2, W2s, H1, 0);
    gemm_hmma<<<dim3(4 * H2 / 64, M_ROWS / 128), 256>>>(
        y1s, W2s, b2, pre2, 4 * H2, 3 * H1);

    lstm_layer2<<<NBLK, 256, smem2>>>(pre2, Whh2, out);
}

// round 15
// speedup vs baseline: 1.8605x; 1.1325x over previous
#include <cuda_runtime.h>
#include <cuda_bf16.h>
#include <math.h>
#include <stdint.h>

#define T_STEPS 16
#define IN_DIM  12288
#define H1 256
#define H2 512
#define BATCH 128
#define M_ROWS (T_STEPS * BATCH)   // 2048
#define NBLK 128
#define PITCH 40
#define STAGES 4

// ---------------- scratch (no cudaMalloc allowed) ----------------
__device__ float g_pre1[M_ROWS * 4 * H1];
__device__ float g_y1  [M_ROWS * H1];
__device__ float g_pre2[M_ROWS * 4 * H2];
__device__ float g_h1[2][H1 * BATCH];
__device__ float g_h2[2][H2 * BATCH];
__device__ unsigned g_cnt1, g_gen1, g_cnt2, g_gen2;

// split-bf16 operands, 3 segments along K:
//   A-side: [hi | lo | hi]   W-side: [hi | hi | lo]
__device__ __nv_bfloat16 g_A1s[M_ROWS * 3 * IN_DIM];
__device__ __nv_bfloat16 g_W1s[4 * H1 * 3 * IN_DIM];
__device__ __nv_bfloat16 g_y1s[M_ROWS * 3 * H1];
__device__ __nv_bfloat16 g_W2s[4 * H2 * 3 * H1];

// ---------------- fp32 -> split bf16 (3 segments along K) ----------------
__global__ void split_bf16(const float* __restrict__ src, __nv_bfloat16* __restrict__ dst,
                           int K, int a_mode) {
    int r = blockIdx.y;
    int k = (blockIdx.x * blockDim.x + threadIdx.x) * 4;
    if (k >= K) return;
    float4 a = *(const float4*)(src + (size_t)r * K + k);
    __nv_bfloat16* d0 = dst + (size_t)r * 3 * K + k;
    __nv_bfloat16* d1 = d0 + K;
    __nv_bfloat16* d2 = d0 + 2 * K;
    float v[4] = {a.x, a.y, a.z, a.w};
    #pragma unroll
    for (int i = 0; i < 4; ++i) {
        __nv_bfloat16 hi = __float2bfloat16(v[i]);
        __nv_bfloat16 lo = __float2bfloat16(v[i] - __bfloat162float(hi));
        d0[i] = hi;
        if (a_mode) { d1[i] = lo; d2[i] = hi; }
        else        { d1[i] = hi; d2[i] = lo; }
    }
}

// ---------------- PTX helpers ----------------
__device__ __forceinline__ uint32_t smem_u32(const void* p) {
    uint32_t a;
    asm("{ .reg .u64 t; cvta.to.shared.u64 t, %1; cvt.u32.u64 %0, t; }" : "=r"(a) : "l"(p));
    return a;
}
__device__ __forceinline__ void ldsm_x4(uint32_t& r0, uint32_t& r1, uint32_t& r2, uint32_t& r3, uint32_t a) {
    asm volatile("ldmatrix.sync.aligned.m8n8.x4.shared.b16 {%0,%1,%2,%3}, [%4];"
                 : "=r"(r0), "=r"(r1), "=r"(r2), "=r"(r3) : "r"(a));
}
__device__ __forceinline__ void mma16816(float* c, const uint32_t* a, const uint32_t* b) {
    asm volatile(
        "mma.sync.aligned.m16n8k16.row.col.f32.bf16.bf16.f32 "
        "{%0,%1,%2,%3}, {%4,%5,%6,%7}, {%8,%9}, {%0,%1,%2,%3};"
        : "+f"(c[0]), "+f"(c[1]), "+f"(c[2]), "+f"(c[3])
        : "r"(a[0]), "r"(a[1]), "r"(a[2]), "r"(a[3]), "r"(b[0]), "r"(b[1]));
}
__device__ __forceinline__ void cp16(uint32_t saddr, const void* gaddr) {
    asm volatile("cp.async.cg.shared.global [%0], [%1], 16;" :: "r"(saddr), "l"(gaddr));
}

// ---------------- HMMA GEMM, cp.async 4-stage: C = A @ W^T + bias ----------------
// 128x128 CTA tile, BK=32, 8 warps (4M x 2N), warp tile 32x64.
// 2 CTAs/SM (launch_bounds reg cap + 80 KB smem/CTA).
__global__ __launch_bounds__(256, 2) void gemm_hmma(
    const __nv_bfloat16* __restrict__ A, const __nv_bfloat16* __restrict__ W,
    const float* __restrict__ bias, float* __restrict__ C, int N, int K2)
{
    extern __shared__ __nv_bfloat16 smb[];   // [STAGES][A:5120 | B:5120] elems
    const int TILE_E = 128 * PITCH;          // 5120 elems = 10240 B per operand tile

    const int tid = threadIdx.x;
    const int lane = tid & 31;
    const int wid = tid >> 5;
    const int moff = (wid >> 1) * 32;
    const int noff = (wid & 1) * 64;
    const int m0 = blockIdx.y * 128;
    const int n0 = blockIdx.x * 128;
    const int NT = K2 >> 5;

    const int r0g = tid >> 2, c0g = (tid & 3) * 8;
    const int r1g = r0g + 64;

    float acc[2][8][4];
    #pragma unroll
    for (int mt = 0; mt < 2; ++mt)
        #pragma unroll
        for (int nt = 0; nt < 8; ++nt)
            #pragma unroll
            for (int i = 0; i < 4; ++i) acc[mt][nt][i] = 0.f;

    const __nv_bfloat16* Ab = A + (size_t)m0 * K2;
    const __nv_bfloat16* Wb = W + (size_t)n0 * K2;

    const uint32_t sA0 = smem_u32(&smb[r0g * PITCH + c0g]);
    const uint32_t sA1 = smem_u32(&smb[r1g * PITCH + c0g]);

    #define ISSUE(kt) do {                                                    \
        int _s = (kt) % STAGES;                                               \
        uint32_t _b = (uint32_t)_s * 2u * TILE_E * 2u;                        \
        int _k0 = (kt) << 5;                                                  \
        cp16(sA0 + _b,              Ab + (size_t)r0g * K2 + _k0 + c0g);       \
        cp16(sA1 + _b,              Ab + (size_t)r1g * K2 + _k0 + c0g);       \
        cp16(sA0 + _b + TILE_E*2u,  Wb + (size_t)r0g * K2 + _k0 + c0g);       \
        cp16(sA1 + _b + TILE_E*2u,  Wb + (size_t)r1g * K2 + _k0 + c0g);       \
        asm volatile("cp.async.commit_group;" ::: "memory");                  \
    } while (0)

    ISSUE(0);
    ISSUE(1);
    ISSUE(2);

    const int lrow = lane & 15;
    const int lhalf = (lane >> 4) * 8;
    const uint32_t smbase = smem_u32(smb);

    for (int kt = 0; kt < NT; ++kt) {
        asm volatile("cp.async.wait_group 2;" ::: "memory");
        __syncthreads();

        const int cur = kt % STAGES;
        const uint32_t sA = smbase + (uint32_t)cur * 2u * TILE_E * 2u;
        const uint32_t sB = sA + TILE_E * 2u;

        #pragma unroll
        for (int ks = 0; ks < 32; ks += 16) {
            uint32_t af[2][4];
            #pragma unroll
            for (int mt = 0; mt < 2; ++mt) {
                uint32_t addr = sA + (uint32_t)((moff + mt * 16 + lrow) * PITCH + ks + lhalf) * 2u;
                ldsm_x4(af[mt][0], af[mt][1], af[mt][2], af[mt][3], addr);
            }
            uint32_t bf[8][2];
            #pragma unroll
            for (int nt2 = 0; nt2 < 4; ++nt2) {
                uint32_t t0, t1, t2, t3;
                uint32_t addr = sB + (uint32_t)((noff + nt2 * 16 + lrow) * PITCH + ks + lhalf) * 2u;
                ldsm_x4(t0, t1, t2, t3, addr);   // NON-trans: W rows are n, k contiguous
                bf[nt2 * 2 + 0][0] = t0; bf[nt2 * 2 + 0][1] = t2;
                bf[nt2 * 2 + 1][0] = t1; bf[nt2 * 2 + 1][1] = t3;
            }
            #pragma unroll
            for (int mt = 0; mt < 2; ++mt)
                #pragma unroll
                for (int nt = 0; nt < 8; ++nt)
                    mma16816(acc[mt][nt], af[mt], bf[nt]);
        }

        if (kt + 3 < NT) {
            ISSUE(kt + 3);
        } else {
            asm volatile("cp.async.commit_group;" ::: "memory");
        }
    }
    #undef ISSUE

    // epilogue: add bias, write C
    const int g = lane >> 2;
    const int tig = lane & 3;
    #pragma unroll
    for (int mt = 0; mt < 2; ++mt) {
        #pragma unroll
        for (int nt = 0; nt < 8; ++nt) {
            int n = n0 + noff + nt * 8 + tig * 2;
            float b0v = bias[n], b1v = bias[n + 1];
            int mA = m0 + moff + mt * 16 + g;
            float2 v0 = { acc[mt][nt][0] + b0v, acc[mt][nt][1] + b1v };
            float2 v1 = { acc[mt][nt][2] + b0v, acc[mt][nt][3] + b1v };
            *(float2*)(C + (size_t)mA * N + n) = v0;
            *(float2*)(C + (size_t)(mA + 8) * N + n) = v1;
        }
    }
}

// ---------------- grid barrier ----------------
__device__ __forceinline__ void grid_sync(unsigned* cnt, unsigned* gen, unsigned& local) {
    __syncthreads();
    if (threadIdx.x == 0) {
        __threadfence();
        if (atomicAdd(cnt, 1u) == NBLK - 1u) {
            atomicExch(cnt, 0u);
            __threadfence();
            atomicAdd(gen, 1u);
        } else {
            while (atomicAdd(gen, 0u) == local) { }
        }
        __threadfence();
    }
    __syncthreads();
    local++;
}

__device__ __forceinline__ float sigf(float x) { return 1.f / (1.f + expf(-x)); }

// ---------------- persistent LSTM layer 1 (H=256) — proven ----------------
__global__ __launch_bounds__(256) void lstm_layer1(
    const float* __restrict__ pre, const float* __restrict__ Whh, float* __restrict__ y1)
{
    extern __shared__ float smemf[];
    float* Wst = smemf;
    float* hs  = smemf + H1 * 8;

    const int tid = threadIdx.x;
    const int bid = blockIdx.x;
    const int b   = tid & 127;
    const int jj  = tid >> 7;
    const int j   = bid * 2 + jj;

    #pragma unroll
    for (int r = 0; r < 8; ++r) {
        int jj2 = r >> 2, g = r & 3;
        const float* wrow = Whh + ((size_t)(g * H1 + bid * 2 + jj2)) * H1;
        for (int k = tid; k < H1; k += 256) Wst[k * 8 + jj2 * 4 + g] = wrow[k];
    }

    __shared__ unsigned s_gen;
    if (tid == 0) s_gen = atomicAdd(&g_gen1, 0u);
    __syncthreads();
    unsigned local = s_gen;

    float c0 = 0.f;

    for (int t = 0; t < T_STEPS; ++t) {
        float a0 = 0.f, a1 = 0.f, a2 = 0.f, a3 = 0.f;
        if (t > 0) {
            const float* hprev = g_h1[(t - 1) & 1];
            for (int k0 = 0; k0 < H1; k0 += 64) {
                const float4* src = (const float4*)(hprev + k0 * BATCH);
                float4* dst = (float4*)hs;
                #pragma unroll
                for (int i = tid; i < 64 * BATCH / 4; i += 256) dst[i] = src[i];
                __syncthreads();
                #pragma unroll 8
                for (int kk = 0; kk < 64; ++kk) {
                    float hv = hs[kk * BATCH + b];
                    float4 w = *(const float4*)(Wst + (size_t)(k0 + kk) * 8 + jj * 4);
                    a0 += w.x * hv; a1 += w.y * hv; a2 += w.z * hv; a3 += w.w * hv;
                }
                __syncthreads();
            }
        }
        const float* p = pre + ((size_t)t * BATCH + b) * (4 * H1);
        float ig = a0 + p[j];
        float fg = a1 + p[H1 + j];
        float gg = a2 + p[2 * H1 + j];
        float og = a3 + p[3 * H1 + j];
        c0 = sigf(fg) * c0 + sigf(ig) * tanhf(gg);
        float h2 = sigf(og) * tanhf(c0);
        y1[((size_t)t * BATCH + b) * H1 + j] = h2;
        if (t < T_STEPS - 1) {
            g_h1[t & 1][j * BATCH + b] = h2;
            grid_sync(&g_cnt1, &g_gen1, local);
        }
    }
}

// ---------------- persistent LSTM layer 2 (H=512) — proven ----------------
__global__ __launch_bounds__(256) void lstm_layer2(
    const float* __restrict__ pre, const float* __restrict__ Whh, float* __restrict__ out)
{
    extern __shared__ float smemf[];
    float* Wst = smemf;
    float* hs  = smemf + H2 * 16;

    const int tid = threadIdx.x;
    const int bid = blockIdx.x;
    const int b   = tid & 127;
    const int jp  = tid >> 7;

    #pragma unroll
    for (int r = 0; r < 16; ++r) {
        int jj = r >> 2, g = r & 3;
        const float* wrow = Whh + ((size_t)(g * H2 + bid * 4 + jj)) * H2;
        for (int k = tid; k < H2; k += 256) Wst[k * 16 + jj * 4 + g] = wrow[k];
    }

    __shared__ unsigned s_gen;
    if (tid == 0) s_gen = atomicAdd(&g_gen2, 0u);
    __syncthreads();
    unsigned local = s_gen;

    float c0 = 0.f, c1 = 0.f;

    for (int t = 0; t < T_STEPS; ++t) {
        float acc[8];
        #pragma unroll
        for (int i = 0; i < 8; ++i) acc[i] = 0.f;

        if (t > 0) {
            const float* hprev = g_h2[(t - 1) & 1];
            for (int k0 = 0; k0 < H2; k0 += 64) {
                const float4* src = (const float4*)(hprev + k0 * BATCH);
                float4* dst = (float4*)hs;
                #pragma unroll
                for (int i = tid; i < 64 * BATCH / 4; i += 256) dst[i] = src[i];
                __syncthreads();
                #pragma unroll 4
                for (int kk = 0; kk < 64; ++kk) {
                    float hv = hs[kk * BATCH + b];
                    const float* wp = Wst + (size_t)(k0 + kk) * 16 + jp * 8;
                    float4 wa = *(const float4*)(wp);
                    float4 wb = *(const float4*)(wp + 4);
                    acc[0] += wa.x * hv; acc[1] += wa.y * hv;
                    acc[2] += wa.z * hv; acc[3] += wa.w * hv;
                    acc[4] += wb.x * hv; acc[5] += wb.y * hv;
                    acc[6] += wb.z * hv; acc[7] += wb.w * hv;
                }
                __syncthreads();
            }
        }

        const float* p = pre + ((size_t)t * BATCH + b) * (4 * H2);
        #pragma unroll
        for (int u = 0; u < 2; ++u) {
            int j = bid * 4 + jp * 2 + u;
            float ig = acc[u * 4 + 0] + p[j];
            float fg = acc[u * 4 + 1] + p[H2 + j];
            float gg = acc[u * 4 + 2] + p[2 * H2 + j];
            float og = acc[u * 4 + 3] + p[3 * H2 + j];
            float c = (u == 0) ? c0 : c1;
            c = sigf(fg) * c + sigf(ig) * tanhf(gg);
            if (u == 0) c0 = c; else c1 = c;
            float h2 = sigf(og) * tanhf(c);
            out[((size_t)t * BATCH + b) * H2 + j] = h2;
            if (t < T_STEPS - 1) g_h2[t & 1][j * BATCH + b] = h2;
        }
        if (t < T_STEPS - 1) grid_sync(&g_cnt2, &g_gen2, local);
    }
}

// ---------------- launch ----------------
extern "C" void kernel_launch(void* const* d_in, const int* in_sizes, int n_in,
                              void* d_out, int out_size)
{
    const float* inp  = (const float*)d_in[0];
    const float* Wih1 = (const float*)d_in[1];
    const float* Whh1 = (const float*)d_in[2];
    const float* b1   = (const float*)d_in[3];
    const float* Wih2 = (const float*)d_in[4];
    const float* Whh2 = (const float*)d_in[5];
    const float* b2   = (const float*)d_in[6];
    float* out = (float*)d_out;

    float *pre1, *y1, *pre2;
    __nv_bfloat16 *A1s, *W1s, *y1s, *W2s;
    cudaGetSymbolAddress((void**)&pre1, g_pre1);
    cudaGetSymbolAddress((void**)&y1,   g_y1);
    cudaGetSymbolAddress((void**)&pre2, g_pre2);
    cudaGetSymbolAddress((void**)&A1s,  g_A1s);
    cudaGetSymbolAddress((void**)&W1s,  g_W1s);
    cudaGetSymbolAddress((void**)&y1s,  g_y1s);
    cudaGetSymbolAddress((void**)&W2s,  g_W2s);

    const int gemm_smem = STAGES * 2 * 128 * PITCH * 2;   // 81920 B
    cudaFuncSetAttribute(gemm_hmma, cudaFuncAttributeMaxDynamicSharedMemorySize, gemm_smem);
    const int smem1 = (H1 * 8 + 64 * BATCH) * sizeof(float);
    const int smem2 = (H2 * 16 + 64 * BATCH) * sizeof(float);
    cudaFuncSetAttribute(lstm_layer2, cudaFuncAttributeMaxDynamicSharedMemorySize, smem2);

    // ---- layer 1 ----
    split_bf16<<<dim3(IN_DIM / 1024, M_ROWS), 256>>>(inp, A1s, IN_DIM, 1);
    split_bf16<<<dim3(IN_DIM / 1024, 4 * H1), 256>>>(Wih1, W1s, IN_DIM, 0);
    gemm_hmma<<<dim3(4 * H1 / 128, M_ROWS / 128), 256, gemm_smem>>>(
        A1s, W1s, b1, pre1, 4 * H1, 3 * IN_DIM);

    lstm_layer1<<<NBLK, 256, smem1>>>(pre1, Whh1, y1);

    // ---- layer 2 ----
    split_bf16<<<dim3(1, M_ROWS), 256>>>(y1, y1s, H1, 1);
    split_bf16<<<dim3(1, 4 * H2), 256>>>(Wih2, W2s, H1, 0);
    gemm_hmma<<<dim3(4 * H2 / 128, M_ROWS / 128), 256, gemm_smem>>>(
        y1s, W2s, b2, pre2, 4 * H2, 3 * H1);

    lstm_layer2<<<NBLK, 256, smem2>>>(pre2, Whh2, out);
}